// round 8
// baseline (speedup 1.0000x reference)
#include <cuda_runtime.h>
#include <cstdint>

// Skeleton forward kinematics: 6d rotations -> world-space joint positions.
// angles: [B, 16, 6] f32   xyz: [1, 16, 3] f32   out: [B, 16, 3] f32
//
// Round-8: persistent blocks (4/SM, 16 warps/SM like v3) + in-place cp.async
// prefetch with ZERO extra smem. Tile split into half-buffers X (joints 0-7)
// and Y (joints 8-15), 12 rows x pitch-129 float4 each. Columns are
// thread-private during compute, so after "all Y reads done" the next tile's
// joints 0-7 stream into Y; after gather, next joints 8-15 stream into X.
// Buffers swap parity each iteration. Also: pw[c] = Rw[c] @ t + pw[p]
// (associativity, -135 FMA) and edge vectors precomputed in smem.

namespace {

constexpr int NJ   = 16;
constexpr int TPB  = 128;
constexpr int PIT  = 129;                       // float4 pitch (odd -> conflict-free)
constexpr int HALF = 12 * PIT;                  // float4s per half-buffer
constexpr size_t SMEM_BYTES = 2 * HALF * sizeof(float4) + 48 * sizeof(float);
constexpr int GRID = 608;                       // 4 blocks/SM x 152 SMs

__device__ __forceinline__ void rot6d(const float* __restrict__ a, float R[9]) {
    float n1 = rsqrtf(a[0] * a[0] + a[1] * a[1] + a[2] * a[2]);
    float b1x = a[0] * n1, b1y = a[1] * n1, b1z = a[2] * n1;
    float d = b1x * a[3] + b1y * a[4] + b1z * a[5];
    float b2x = a[3] - d * b1x, b2y = a[4] - d * b1y, b2z = a[5] - d * b1z;
    float n2 = rsqrtf(b2x * b2x + b2y * b2y + b2z * b2z);
    b2x *= n2; b2y *= n2; b2z *= n2;
    R[0] = b1x; R[1] = b1y; R[2] = b1z;
    R[3] = b2x; R[4] = b2y; R[5] = b2z;
    R[6] = b1y * b2z - b1z * b2y;
    R[7] = b1z * b2x - b1x * b2z;
    R[8] = b1x * b2y - b1y * b2x;
}

// Stage 12 rows (one half: joints half*8..half*8+7) of tile at eBase into buf.
__device__ __forceinline__ void stage_half(float4* __restrict__ buf,
                                           const float4* __restrict__ angles4,
                                           size_t eBase, int half, int t) {
    const float4* __restrict__ src = angles4 + eBase * 24 + half * 12;
#pragma unroll
    for (int k = 0; k < 12; ++k) {
        int g = t + k * TPB;                 // 0..1535
        int b = g / 12;
        int r = g - b * 12;
        uint32_t saddr = (uint32_t)__cvta_generic_to_shared(buf + r * PIT + b);
        asm volatile("cp.async.cg.shared.global [%0], [%1], 16;"
                     :: "r"(saddr), "l"(src + (size_t)b * 24 + r) : "memory");
    }
    asm volatile("cp.async.commit_group;" ::: "memory");
}

__global__ __launch_bounds__(TPB, 4)
void skeleton_fk_v8(const float4* __restrict__ angles4,
                    const float*  __restrict__ xyz,
                    float4* __restrict__ out4,
                    int numTiles)
{
    extern __shared__ float4 smem[];
    float4* bufA = smem;                 // half-buffer 0
    float4* bufB = smem + HALF;          // half-buffer 1
    float*  stv  = reinterpret_cast<float*>(smem + 2 * HALF);  // [48]

    const int t = threadIdx.x;

    // Edge vectors: stv[0..2] = ref[0]; stv[3c+k] = ref[c]-ref[parent(c)].
    {
        constexpr int PARENT[15] = {0, 1, 2, 3, 4, 3, 6, 7, 8, 9, 3, 11, 12, 13, 14};
        if (t < 3) stv[t] = __ldg(xyz + t);
        else if (t < 48) {
            int i = t - 3;
            int e = i / 3, k = i - 3 * e;
            stv[t] = __ldg(xyz + 3 * (e + 1) + k) - __ldg(xyz + 3 * PARENT[e] + k);
        }
    }

    int tile = blockIdx.x;
    const int stride = gridDim.x;
    if (tile >= numTiles) return;        // block-uniform

    // Prologue: X <- joints 0-7, Y <- joints 8-15 of first tile.
    float4* X = bufA;
    float4* Y = bufB;
    stage_half(X, angles4, (size_t)tile * TPB, 0, t);   // group: X
    stage_half(Y, angles4, (size_t)tile * TPB, 1, t);   // group: Y

    for (;;) {
        const int  next  = tile + stride;
        const bool more  = (next < numTiles);

        asm volatile("cp.async.wait_group 1;" ::: "memory");   // X ready
        __syncthreads();                                       // S1

        float a2[12];
        float pw[48];
        float Rc[9], Rs[9];

        auto loadPairX = [&](int p) {        // pairs 0..3 from X
            float4 q0 = X[(3 * p + 0) * PIT + t];
            float4 q1 = X[(3 * p + 1) * PIT + t];
            float4 q2 = X[(3 * p + 2) * PIT + t];
            a2[0] = q0.x; a2[1] = q0.y; a2[2]  = q0.z; a2[3]  = q0.w;
            a2[4] = q1.x; a2[5] = q1.y; a2[6]  = q1.z; a2[7]  = q1.w;
            a2[8] = q2.x; a2[9] = q2.y; a2[10] = q2.z; a2[11] = q2.w;
        };
        auto loadPairY = [&](int p) {        // pairs 4..7 from Y (p = 4..7)
            int q = p - 4;
            float4 q0 = Y[(3 * q + 0) * PIT + t];
            float4 q1 = Y[(3 * q + 1) * PIT + t];
            float4 q2 = Y[(3 * q + 2) * PIT + t];
            a2[0] = q0.x; a2[1] = q0.y; a2[2]  = q0.z; a2[3]  = q0.w;
            a2[4] = q1.x; a2[5] = q1.y; a2[6]  = q1.z; a2[7]  = q1.w;
            a2[8] = q2.x; a2[9] = q2.y; a2[10] = q2.z; a2[11] = q2.w;
        };
        auto flushRow = [&](int r) {         // pw float4 r -> X (own column)
            X[r * PIT + t] = make_float4(pw[4 * r + 0], pw[4 * r + 1],
                                         pw[4 * r + 2], pw[4 * r + 3]);
        };
        auto step = [&](int p, int c, int ao) {
            float R[9];
            rot6d(&a2[ao], R);
            float Rn[9];
#pragma unroll
            for (int i = 0; i < 3; ++i)
#pragma unroll
                for (int k = 0; k < 3; ++k)
                    Rn[3 * i + k] = Rc[3 * i + 0] * R[0 + k]
                                  + Rc[3 * i + 1] * R[3 + k]
                                  + Rc[3 * i + 2] * R[6 + k];
            float tx = stv[3 * c + 0], ty = stv[3 * c + 1], tz = stv[3 * c + 2];
            pw[3 * c + 0] = Rn[0] * tx + Rn[1] * ty + Rn[2] * tz + pw[3 * p + 0];
            pw[3 * c + 1] = Rn[3] * tx + Rn[4] * ty + Rn[5] * tz + pw[3 * p + 1];
            pw[3 * c + 2] = Rn[6] * tx + Rn[7] * ty + Rn[8] * tz + pw[3 * p + 2];
#pragma unroll
            for (int i = 0; i < 9; ++i) Rc[i] = Rn[i];
        };

        // ---- Phase 1: joints 0-7 (X) ----
        loadPairX(0);
        rot6d(&a2[0], Rc);
        {
            float x = stv[0], y = stv[1], z = stv[2];
            pw[0] = Rc[0] * x + Rc[1] * y + Rc[2] * z;
            pw[1] = Rc[3] * x + Rc[4] * y + Rc[5] * z;
            pw[2] = Rc[6] * x + Rc[7] * y + Rc[8] * z;
        }
        step(0, 1, 6);  flushRow(0);
        loadPairX(1);
        step(1, 2, 0);  flushRow(1);
        step(2, 3, 6);  flushRow(2);
#pragma unroll
        for (int i = 0; i < 9; ++i) Rs[i] = Rc[i];

        loadPairX(2);
        step(3, 4, 0);
        step(4, 5, 6);  flushRow(3);

#pragma unroll
        for (int i = 0; i < 9; ++i) Rc[i] = Rs[i];
        loadPairX(3);
        step(3, 6, 0);  flushRow(4);
        step(6, 7, 6);  flushRow(5);

        // ---- Phase 2: joints 8-15 (Y) ----
        asm volatile("cp.async.wait_group 0;" ::: "memory");   // Y ready
        __syncthreads();                                       // S2

        loadPairY(4);
        step(7, 8, 0);
        step(8, 9, 6);  flushRow(6);
        loadPairY(5);
        step(9, 10, 0); flushRow(7);

#pragma unroll
        for (int i = 0; i < 9; ++i) Rc[i] = Rs[i];
        step(3, 11, 6);  flushRow(8);
        loadPairY(6);
        step(11, 12, 0);
        step(12, 13, 6); flushRow(9);
        loadPairY(7);                       // last Y read of this thread

        __syncthreads();                                       // S3: all Y reads done
        if (more)                           // prefetch next joints 0-7 into Y
            stage_half(Y, angles4, (size_t)next * TPB, 0, t);

        step(13, 14, 0); flushRow(10);
        step(14, 15, 6); flushRow(11);

        __syncthreads();                                       // S4: pw complete in X

        // ---- Gather: X rows 0-11, coalesced STG.128 ----
        float4* __restrict__ dst = out4 + (size_t)tile * TPB * 12;
#pragma unroll
        for (int k = 0; k < 12; ++k) {
            int g = t + k * TPB;            // 0..1535
            int b = g / 12;
            int r = g - b * 12;
            dst[g] = X[r * PIT + b];
        }

        if (!more) break;

        __syncthreads();                                       // S5: all X reads done
        stage_half(X, angles4, (size_t)next * TPB, 1, t);      // next joints 8-15 -> X

        // Swap: next iteration's j0-7 live in old Y, j8-15 in old X.
        float4* tmp = X; X = Y; Y = tmp;
        tile = next;
    }
}

// Tail fallback (batch not a multiple of TPB; unused for BATCH=262144).
__global__ void skeleton_fk_tail(const float* __restrict__ angles,
                                 const float* __restrict__ xyz,
                                 float* __restrict__ out,
                                 int start, int batch)
{
    int b = start + blockIdx.x * blockDim.x + threadIdx.x;
    if (b >= batch) return;
    const float* ab = angles + (size_t)b * (NJ * 6);
    float ref[NJ * 3];
#pragma unroll
    for (int i = 0; i < NJ * 3; ++i) ref[i] = __ldg(xyz + i);

    float Rw[NJ * 9], pw[NJ * 3];
    {
        float a[6];
#pragma unroll
        for (int k = 0; k < 6; ++k) a[k] = ab[k];
        rot6d(a, &Rw[0]);
        float x = ref[0], y = ref[1], z = ref[2];
        pw[0] = Rw[0] * x + Rw[1] * y + Rw[2] * z;
        pw[1] = Rw[3] * x + Rw[4] * y + Rw[5] * z;
        pw[2] = Rw[6] * x + Rw[7] * y + Rw[8] * z;
    }
    constexpr int PARENT[15] = {0, 1, 2, 3, 4, 3, 6, 7, 8, 9, 3, 11, 12, 13, 14};
#pragma unroll
    for (int e = 0; e < 15; ++e) {
        const int p = PARENT[e], c = e + 1;
        float a[6];
#pragma unroll
        for (int k = 0; k < 6; ++k) a[k] = ab[6 * c + k];
        float R[9]; rot6d(a, R);
        float tx = ref[3 * c + 0] - ref[3 * p + 0];
        float ty = ref[3 * c + 1] - ref[3 * p + 1];
        float tz = ref[3 * c + 2] - ref[3 * p + 2];
        const float* pR = &Rw[9 * p];
        float* nR = &Rw[9 * c];
#pragma unroll
        for (int i = 0; i < 3; ++i)
#pragma unroll
            for (int k = 0; k < 3; ++k)
                nR[3 * i + k] = pR[3 * i + 0] * R[k] + pR[3 * i + 1] * R[3 + k]
                              + pR[3 * i + 2] * R[6 + k];
        pw[3 * c + 0] = nR[0] * tx + nR[1] * ty + nR[2] * tz + pw[3 * p + 0];
        pw[3 * c + 1] = nR[3] * tx + nR[4] * ty + nR[5] * tz + pw[3 * p + 1];
        pw[3 * c + 2] = nR[6] * tx + nR[7] * ty + nR[8] * tz + pw[3 * p + 2];
    }
    float* o = out + (size_t)b * (NJ * 3);
#pragma unroll
    for (int i = 0; i < NJ * 3; ++i) o[i] = pw[i];
}

}  // namespace

extern "C" void kernel_launch(void* const* d_in, const int* in_sizes, int n_in,
                              void* d_out, int out_size) {
    const float* angles = (const float*)d_in[0];
    const float* xyz    = (const float*)d_in[1];
    float* out          = (float*)d_out;

    const int batch    = in_sizes[0] / (NJ * 6);
    const int numTiles = batch / TPB;

    cudaFuncSetAttribute(skeleton_fk_v8,
                         cudaFuncAttributeMaxDynamicSharedMemorySize,
                         (int)SMEM_BYTES);

    if (numTiles > 0) {
        int grid = numTiles < GRID ? numTiles : GRID;
        skeleton_fk_v8<<<grid, TPB, SMEM_BYTES>>>(
            (const float4*)angles, xyz, (float4*)out, numTiles);
    }
    const int rem = batch - numTiles * TPB;
    if (rem > 0) {
        skeleton_fk_tail<<<(rem + 127) / 128, 128>>>(angles, xyz, out,
                                                     numTiles * TPB, batch);
    }
}